// round 2
// baseline (speedup 1.0000x reference)
#include <cuda_runtime.h>

// MomentumLIF: N=64, T=64, D=8192
//   v_t = mom * v_{t-1} + x_t - lamb * u_{t-1}
//   u_t = (1 - 1/tau) * u_{t-1} + v_t         (tau = 2 -> decay = 0.5)
//   s_t = (u_t >= 1.0)
//   u_t = u_t * (1 - s_t)
//
// One thread handles 4 consecutive d-elements (float4) for one n,
// scanning all T=64 steps with register-resident state.

#define N_ 64
#define T_ 64
#define D_ 8192
#define DECAY_ 0.5f
#define TH_ 1.0f

__global__ __launch_bounds__(256)
void momentum_lif_kernel(const float* __restrict__ x,
                         const float* __restrict__ mom_p,
                         const float* __restrict__ lamb_p,
                         float* __restrict__ out)
{
    // vector lane index over N * (D/4)
    const int vid = blockIdx.x * blockDim.x + threadIdx.x;
    const int vecD = D_ / 4;                 // 2048 float4 per row
    const int n = vid / vecD;
    const int dv = vid - n * vecD;

    const float mom = __ldg(mom_p);
    const float lb  = __ldg(lamb_p);

    const float4* xin  = reinterpret_cast<const float4*>(x)   + (size_t)n * T_ * vecD + dv;
    float4*       oout = reinterpret_cast<float4*>(out)        + (size_t)n * T_ * vecD + dv;

    float u0 = 0.f, u1 = 0.f, u2 = 0.f, u3 = 0.f;
    float v0 = 0.f, v1 = 0.f, v2 = 0.f, v3 = 0.f;

    #pragma unroll 8
    for (int t = 0; t < T_; ++t) {
        const float4 xt = xin[(size_t)t * vecD];

        v0 = mom * v0 + xt.x - lb * u0;
        v1 = mom * v1 + xt.y - lb * u1;
        v2 = mom * v2 + xt.z - lb * u2;
        v3 = mom * v3 + xt.w - lb * u3;

        u0 = DECAY_ * u0 + v0;
        u1 = DECAY_ * u1 + v1;
        u2 = DECAY_ * u2 + v2;
        u3 = DECAY_ * u3 + v3;

        float4 s;
        s.x = (u0 >= TH_) ? 1.0f : 0.0f;
        s.y = (u1 >= TH_) ? 1.0f : 0.0f;
        s.z = (u2 >= TH_) ? 1.0f : 0.0f;
        s.w = (u3 >= TH_) ? 1.0f : 0.0f;

        // hard reset
        u0 = (s.x != 0.0f) ? 0.0f : u0;
        u1 = (s.y != 0.0f) ? 0.0f : u1;
        u2 = (s.z != 0.0f) ? 0.0f : u2;
        u3 = (s.w != 0.0f) ? 0.0f : u3;

        oout[(size_t)t * vecD] = s;
    }
}

extern "C" void kernel_launch(void* const* d_in, const int* in_sizes, int n_in,
                              void* d_out, int out_size)
{
    const float* x    = (const float*)d_in[0];
    const float* mom  = (const float*)d_in[1];
    const float* lamb = (const float*)d_in[2];
    float* out        = (float*)d_out;

    const int total_vec = N_ * (D_ / 4);     // 131072 threads
    const int threads = 256;
    const int blocks = total_vec / threads;  // 512

    momentum_lif_kernel<<<blocks, threads>>>(x, mom, lamb, out);
}